// round 4
// baseline (speedup 1.0000x reference)
#include <cuda_runtime.h>

// Problem constants (fixed by the reference)
#define BATCH   2048
#define NSIZE   1024     // INPUTSIZE == OUTPUTSIZE
#define FMAPS   16
#define NBITS   10

#define TPB        256   // threads per block
#define ROWS_STAGE 8     // x rows staged in smem per sync window (32 KB)
#define ROWS_TILE  56    // batch rows per block
#define NTILES     ((BATCH + ROWS_TILE - 1) / ROWS_TILE)   // 37
#define FPT        4     // features per thread

// ---- packed f32x2 helpers (sm_10x; ptxas will NOT auto-fuse, must be PTX) ----
__device__ __forceinline__ void fma2(unsigned long long &d,
                                     unsigned long long a,
                                     unsigned long long b) {
    asm("fma.rn.f32x2 %0, %1, %2, %0;" : "+l"(d) : "l"(a), "l"(b));
}
__device__ __forceinline__ unsigned long long add2(unsigned long long a,
                                                   unsigned long long b) {
    unsigned long long d;
    asm("add.rn.f32x2 %0, %1, %2;" : "=l"(d) : "l"(a), "l"(b));
    return d;
}
// swap the two f32 halves of a packed pair (register-pair shuffle, ~free)
__device__ __forceinline__ unsigned long long swap2(unsigned long long v) {
    unsigned int lo = (unsigned int)v;
    unsigned int hi = (unsigned int)(v >> 32);
    unsigned long long d;
    asm("mov.b64 %0, {%1, %2};" : "=l"(d) : "r"(hi), "r"(lo));
    return d;
}

// out[b, f*1024+o] = bias[f,o] + x[b,o] + sum_j x[b, o^2^j] * w[f,j,o]
__global__ __launch_bounds__(TPB)
void hypercube_kernel(const float* __restrict__ x,
                      const float* __restrict__ w,
                      const float* __restrict__ bias,
                      float* __restrict__ out) {
    __shared__ float xs[ROWS_STAGE * NSIZE];     // 32 KB staged x rows

    const int tid  = threadIdx.x;
    const int och  = blockIdx.x & 1;             // which half of the o range
    const int fg   = blockIdx.x >> 1;            // feature group 0..3
    const int tile = blockIdx.y;                 // batch tile

    const int p  = och * TPB + tid;              // o-pair index, 0..511 (o = 2p, 2p+1)
    const int f0 = fg * FPT;

    // ---- weights + bias for (4 features) x (10 bits) x (this o-pair) into registers ----
    unsigned long long wr[FPT][NBITS];
    unsigned long long br[FPT];
#pragma unroll
    for (int f = 0; f < FPT; f++) {
#pragma unroll
        for (int j = 0; j < NBITS; j++) {
            wr[f][j] = *(const unsigned long long*)(w + ((size_t)(f0 + f) * NBITS + j) * NSIZE + 2 * p);
        }
        br[f] = *(const unsigned long long*)(bias + (size_t)(f0 + f) * NSIZE + 2 * p);
    }

    const int bstart = tile * ROWS_TILE;
    const int rows   = min(ROWS_TILE, BATCH - bstart);

    for (int r0 = 0; r0 < rows; r0 += ROWS_STAGE) {
        const int rcnt = min(ROWS_STAGE, rows - r0);

        // stage rcnt full x rows (float4, fully coalesced; x rows are contiguous)
        {
            const float4* src = (const float4*)(x + (size_t)(bstart + r0) * NSIZE);
            float4* dst = (float4*)xs;
            const int n4 = rcnt * (NSIZE / 4);
            for (int i = tid; i < n4; i += TPB) dst[i] = src[i];
        }
        __syncthreads();

        for (int r = 0; r < rcnt; r++) {
            const unsigned long long* row = (const unsigned long long*)(xs + r * NSIZE);

            // gather the 10 hypercube-neighbor pairs (LDS.64, conflict-free xor perm)
            const unsigned long long x0 = row[p];
            unsigned long long xg[NBITS];
            xg[0] = swap2(x0);                           // o^1 swaps within the pair
#pragma unroll
            for (int j = 1; j < NBITS; j++)
                xg[j] = row[p ^ (1 << (j - 1))];         // o^2^j -> pair p^2^(j-1)

            unsigned long long acc[FPT];
#pragma unroll
            for (int f = 0; f < FPT; f++) acc[f] = add2(br[f], x0);  // bias + skip term
#pragma unroll
            for (int j = 0; j < NBITS; j++)
#pragma unroll
                for (int f = 0; f < FPT; f++)
                    fma2(acc[f], xg[j], wr[f][j]);

            float* orow = out + (size_t)(bstart + r0 + r) * (FMAPS * NSIZE);
#pragma unroll
            for (int f = 0; f < FPT; f++)
                *(unsigned long long*)(orow + (size_t)(f0 + f) * NSIZE + 2 * p) = acc[f];
        }
        __syncthreads();
    }
}

extern "C" void kernel_launch(void* const* d_in, const int* in_sizes, int n_in,
                              void* d_out, int out_size) {
    (void)in_sizes; (void)n_in; (void)out_size;
    const float* x    = (const float*)d_in[0];   // [2048,1024] f32
    const float* w    = (const float*)d_in[1];   // [16,10,1024] f32
    const float* bias = (const float*)d_in[2];   // [16,1024] f32
    // d_in[3] = fm (int32) — analytically (o ^ 2^j) % 1024, not needed
    float* out = (float*)d_out;                  // [2048, 16384] f32

    dim3 grid(8, NTILES);                        // 2 o-halves * 4 f-groups, 37 batch tiles
    hypercube_kernel<<<grid, TPB>>>(x, w, bias, out);
}

// round 5
// speedup vs baseline: 1.2097x; 1.2097x over previous
#include <cuda_runtime.h>
#include <cstdint>

// Problem constants (fixed by the reference)
#define BATCH   2048
#define NSIZE   1024     // INPUTSIZE == OUTPUTSIZE
#define FMAPS   16
#define NBITS   10

#define TPB        256   // threads per block
#define RSTAGE     4     // x rows per pipeline stage (16 KB per buffer)
#define ROWS_TILE  56    // batch rows per block (divisible by RSTAGE; last tile = 32, also ok)
#define NTILES     ((BATCH + ROWS_TILE - 1) / ROWS_TILE)   // 37 -> 8*37 = 296 CTAs = one full wave
#define FPT        4     // features per thread

typedef unsigned long long u64;

// ---- packed f32x2 helpers (sm_10x; ptxas will NOT auto-fuse, must be PTX) ----
__device__ __forceinline__ void fma2(u64 &d, u64 a, u64 b) {
    asm("fma.rn.f32x2 %0, %1, %2, %0;" : "+l"(d) : "l"(a), "l"(b));
}
__device__ __forceinline__ u64 add2(u64 a, u64 b) {
    u64 d;
    asm("add.rn.f32x2 %0, %1, %2;" : "=l"(d) : "l"(a), "l"(b));
    return d;
}
__device__ __forceinline__ u64 swap2(u64 v) {   // swap the two f32 halves (pair-xor by 1)
    unsigned int lo = (unsigned int)v, hi = (unsigned int)(v >> 32);
    u64 d;
    asm("mov.b64 %0, {%1, %2};" : "=l"(d) : "r"(hi), "r"(lo));
    return d;
}

// ---- cp.async staging helpers ----
__device__ __forceinline__ uint32_t smem_u32(const void* p) {
    uint32_t a;
    asm("{ .reg .u64 t; cvta.to.shared.u64 t, %1; cvt.u32.u64 %0, t; }" : "=r"(a) : "l"(p));
    return a;
}
__device__ __forceinline__ void cp_async16(uint32_t dst, const void* src) {
    asm volatile("cp.async.cg.shared.global [%0], [%1], 16;" :: "r"(dst), "l"(src));
}
#define CP_COMMIT() asm volatile("cp.async.commit_group;")
#define CP_WAIT1()  asm volatile("cp.async.wait_group 1;" ::: "memory")

// out[b, f*1024+o] = bias[f,o] + x[b,o] + sum_j x[b, o^2^j] * w[f,j,o]
__global__ __launch_bounds__(TPB, 2)
void hypercube_kernel(const float* __restrict__ x,
                      const float* __restrict__ w,
                      const float* __restrict__ bias,
                      float* __restrict__ out) {
    __shared__ float xs[2][RSTAGE * NSIZE];      // 2 x 16 KB double-buffered x rows

    const int tid  = threadIdx.x;
    const int och  = blockIdx.x & 1;             // which half of the o range
    const int fg   = blockIdx.x >> 1;            // feature group 0..3
    const int tile = blockIdx.y;                 // batch tile

    const int p  = och * TPB + tid;              // o-pair index 0..511 (o = 2p, 2p+1)
    const int f0 = fg * FPT;

    // ---- weights + bias for (4 features) x (10 bits) x (this o-pair) into registers ----
    u64 wr[FPT][NBITS];
    u64 br[FPT];
#pragma unroll
    for (int f = 0; f < FPT; f++) {
#pragma unroll
        for (int j = 0; j < NBITS; j++)
            wr[f][j] = *(const u64*)(w + ((size_t)(f0 + f) * NBITS + j) * NSIZE + 2 * p);
        br[f] = *(const u64*)(bias + (size_t)(f0 + f) * NSIZE + 2 * p);
    }

    const int bstart = tile * ROWS_TILE;
    const int rows   = min(ROWS_TILE, BATCH - bstart);   // 56, or 32 for the last tile
    const int ns     = rows / RSTAGE;                    // stages (rows always % 4 == 0)

    const uint32_t xs_base = smem_u32(&xs[0][0]);

    // prologue: stages 0 and 1 in flight
    {
        const char* src0 = (const char*)(x + (size_t)bstart * NSIZE);
#pragma unroll
        for (int i = tid; i < RSTAGE * NSIZE / 4; i += TPB)
            cp_async16(xs_base + i * 16, src0 + i * 16);
        CP_COMMIT();
        if (ns > 1) {
            const char* src1 = (const char*)(x + (size_t)(bstart + RSTAGE) * NSIZE);
#pragma unroll
            for (int i = tid; i < RSTAGE * NSIZE / 4; i += TPB)
                cp_async16(xs_base + RSTAGE * NSIZE * 4 + i * 16, src1 + i * 16);
        }
        CP_COMMIT();
    }

    for (int s = 0; s < ns; s++) {
        const int b = s & 1;
        CP_WAIT1();                 // stage s (issued 2 iterations ago) is complete
        __syncthreads();

        const u64* base = (const u64*)(&xs[b][0]);

        // process 4 rows, 2 at a time (8 independent accumulator chains)
#pragma unroll
        for (int r = 0; r < RSTAGE; r += 2) {
            const u64* rowA = base + r * (NSIZE / 2);
            const u64* rowB = rowA + (NSIZE / 2);

            const u64 xA = rowA[p];
            const u64 xB = rowB[p];

            u64 aA[FPT], aB[FPT];
#pragma unroll
            for (int f = 0; f < FPT; f++) {      // bias + skip term
                aA[f] = add2(br[f], xA);
                aB[f] = add2(br[f], xB);
            }
            {                                     // j = 0: o^1 = in-pair swap (free)
                const u64 gA = swap2(xA), gB = swap2(xB);
#pragma unroll
                for (int f = 0; f < FPT; f++) {
                    fma2(aA[f], gA, wr[f][0]);
                    fma2(aB[f], gB, wr[f][0]);
                }
            }
#pragma unroll
            for (int j = 1; j < NBITS; j++) {     // xor-neighbor pair gathers (LDS.64, conflict-free)
                const int q = p ^ (1 << (j - 1));
                const u64 gA = rowA[q];
                const u64 gB = rowB[q];
#pragma unroll
                for (int f = 0; f < FPT; f++) {
                    fma2(aA[f], gA, wr[f][j]);
                    fma2(aB[f], gB, wr[f][j]);
                }
            }

            float* oA = out + (size_t)(bstart + s * RSTAGE + r) * (FMAPS * NSIZE);
            float* oB = oA + (FMAPS * NSIZE);
#pragma unroll
            for (int f = 0; f < FPT; f++) {
                *(u64*)(oA + (size_t)(f0 + f) * NSIZE + 2 * p) = aA[f];
                *(u64*)(oB + (size_t)(f0 + f) * NSIZE + 2 * p) = aB[f];
            }
        }

        __syncthreads();            // everyone done reading buffer b before refilling it
        if (s + 2 < ns) {
            const char* src = (const char*)(x + (size_t)(bstart + (s + 2) * RSTAGE) * NSIZE);
            const uint32_t dst = xs_base + b * (RSTAGE * NSIZE * 4);
#pragma unroll
            for (int i = tid; i < RSTAGE * NSIZE / 4; i += TPB)
                cp_async16(dst + i * 16, src + i * 16);
        }
        CP_COMMIT();                // commit even when empty to keep group counts aligned
    }
}

extern "C" void kernel_launch(void* const* d_in, const int* in_sizes, int n_in,
                              void* d_out, int out_size) {
    (void)in_sizes; (void)n_in; (void)out_size;
    const float* x    = (const float*)d_in[0];   // [2048,1024] f32
    const float* w    = (const float*)d_in[1];   // [16,10,1024] f32
    const float* bias = (const float*)d_in[2];   // [16,1024] f32
    // d_in[3] = fm (int32) — analytically (o ^ 2^j) % 1024, not needed
    float* out = (float*)d_out;                  // [2048, 16384] f32

    dim3 grid(8, NTILES);                        // 2 o-halves * 4 f-groups, 37 batch tiles
    hypercube_kernel<<<grid, TPB>>>(x, w, bias, out);
}